// round 10
// baseline (speedup 1.0000x reference)
#include <cuda_runtime.h>
#include <cuda_bf16.h>
#include <cstdint>

#define H        128
#define NE       500000
#define NN       50000
#define APAD     68                  // padded b32-pair row stride (64 + 4)

// ---------------- scratch (__device__ globals) ----------------
__device__ __align__(16) float g_U[NN * H];
__device__ __align__(16) float g_V[NN * H];
__device__ __align__(16) float g_S[NN * H];
__device__ __align__(16) float g_sumw[NN];
__device__ __align__(16) uint32_t g_B1u[32768];   // [hl][kt8][nt32][lane32][2]
__device__ __align__(16) uint32_t g_B2u[16384];   // [hl][kt8][nt16][lane32][2]
// CSR scratch
__device__ __align__(16) int   g_cnt[NN];
__device__ __align__(16) int   g_off[NN + 1];
__device__ __align__(16) int   g_cur[NN];
__device__ __align__(16) int   g_esrc[NE];
__device__ __align__(16) float g_eaw[NE];

// ---------------- helpers ----------------
__device__ __forceinline__ void splitpair(float v0, float v1, uint32_t& h, uint32_t& l) {
    __nv_bfloat162 hh = __floats2bfloat162_rn(v0, v1);
    float r0 = v0 - __bfloat162float(hh.x);
    float r1 = v1 - __bfloat162float(hh.y);
    __nv_bfloat162 ll = __floats2bfloat162_rn(r0, r1);
    h = *(uint32_t*)&hh;
    l = *(uint32_t*)&ll;
}

__device__ __forceinline__ void mma_bf16(float* d,
                                         uint32_t a0, uint32_t a1, uint32_t a2, uint32_t a3,
                                         uint32_t b0, uint32_t b1) {
    asm("mma.sync.aligned.m16n8k16.row.col.f32.bf16.bf16.f32 "
        "{%0,%1,%2,%3}, {%4,%5,%6,%7}, {%8,%9}, {%0,%1,%2,%3};"
        : "+f"(d[0]), "+f"(d[1]), "+f"(d[2]), "+f"(d[3])
        : "r"(a0), "r"(a1), "r"(a2), "r"(a3), "r"(b0), "r"(b1));
}

// ---------------- CSR build ----------------
__global__ void zero_cnt_kernel() {
    int i = blockIdx.x * blockDim.x + threadIdx.x;
    if (i < NN) g_cnt[i] = 0;
}

__global__ void hist_kernel(const int* __restrict__ ei) {
    int e = blockIdx.x * blockDim.x + threadIdx.x;
    if (e < NE) atomicAdd(&g_cnt[ei[NE + e]], 1);
}

__global__ void scan_kernel() {     // single CTA, 1024 threads
    __shared__ int wsum[32];
    __shared__ int running_s;
    const int tid = threadIdx.x, lane = tid & 31, wid = tid >> 5;
    if (tid == 0) running_s = 0;
    __syncthreads();
    for (int base = 0; base < NN; base += 1024) {
        int idx = base + tid;
        int v = (idx < NN) ? g_cnt[idx] : 0;
        int incl = v;
        #pragma unroll
        for (int o = 1; o < 32; o <<= 1) {
            int n = __shfl_up_sync(0xFFFFFFFFu, incl, o);
            if (lane >= o) incl += n;
        }
        if (lane == 31) wsum[wid] = incl;
        __syncthreads();
        if (wid == 0) {
            int s = wsum[lane];
            #pragma unroll
            for (int o = 1; o < 32; o <<= 1) {
                int n = __shfl_up_sync(0xFFFFFFFFu, s, o);
                if (lane >= o) s += n;
            }
            wsum[lane] = s;
        }
        __syncthreads();
        int wpre = (wid > 0) ? wsum[wid - 1] : 0;
        int excl = running_s + wpre + incl - v;
        if (idx < NN) { g_off[idx] = excl; g_cur[idx] = excl; }
        __syncthreads();
        if (tid == 0) running_s += wsum[31];
        __syncthreads();
    }
    if (tid == 0) g_off[NN] = running_s;
}

__global__ void scatter_kernel(const int* __restrict__ ei, const float* __restrict__ ea) {
    int e = blockIdx.x * blockDim.x + threadIdx.x;
    if (e < NE) {
        int d = ei[NE + e];
        int pos = atomicAdd(&g_cur[d], 1);
        g_esrc[pos] = ei[e];
        g_eaw[pos]  = ea[e];
    }
}

// ---------------- prep: weight matrices -> bf16 hi/lo fragment images ----------------
__global__ void prep_B1(const float* __restrict__ W1) {   // [256,128]; Bcat[k][n]
    int i = blockIdx.x * blockDim.x + threadIdx.x;
    if (i >= 8192) return;
    int kt = i >> 10, nt = (i >> 5) & 31, lane = i & 31;
    int g = lane >> 2, tig = lane & 3;
    int n = nt * 8 + g;
    int k0 = kt * 16 + 2 * tig;
    float w[4];
    #pragma unroll
    for (int j = 0; j < 4; j++) {
        int k = k0 + (j >> 1) * 8 + (j & 1);
        w[j] = (n < 128) ? W1[(size_t)k * 128 + n]
                         : W1[(size_t)(128 + k) * 128 + (n - 128)];
    }
    uint32_t b0h, b0l, b1h, b1l;
    splitpair(w[0], w[1], b0h, b0l);
    splitpair(w[2], w[3], b1h, b1l);
    int base = ((kt * 32 + nt) * 32 + lane) * 2;
    g_B1u[base] = b0h; g_B1u[base + 1] = b1h;
    g_B1u[16384 + base] = b0l; g_B1u[16384 + base + 1] = b1l;
}

__global__ void prep_B2(const float* __restrict__ W2) {   // [128,128]
    int i = blockIdx.x * blockDim.x + threadIdx.x;
    if (i >= 4096) return;
    int kt = i >> 9, nt = (i >> 5) & 15, lane = i & 31;
    int g = lane >> 2, tig = lane & 3;
    int n = nt * 8 + g;
    int k0 = kt * 16 + 2 * tig;
    float w[4];
    #pragma unroll
    for (int j = 0; j < 4; j++) {
        int k = k0 + (j >> 1) * 8 + (j & 1);
        w[j] = W2[(size_t)k * 128 + n];
    }
    uint32_t b0h, b0l, b1h, b1l;
    splitpair(w[0], w[1], b0h, b0l);
    splitpair(w[2], w[3], b1h, b1l);
    int base = ((kt * 16 + nt) * 32 + lane) * 2;
    g_B2u[base] = b0h; g_B2u[base + 1] = b1h;
    g_B2u[8192 + base] = b0l; g_B2u[8192 + base + 1] = b1l;
}

// ---------------- GEMM1 (mma): U = x@W1a + b1 ; V = x@W1b ----------------
__global__ __launch_bounds__(256, 3)
void gemm1_kernel(const float* __restrict__ x, const float* __restrict__ b1) {
    extern __shared__ uint32_t sm[];
    uint32_t* sAh = sm;              // 128*68 = 8704
    uint32_t* sAl = sm + 8704;
    const int tid = threadIdx.x;
    const int rbase = blockIdx.x * 128;

    for (int i = tid; i < 128 * 32; i += 256) {
        int r = i >> 5, c4 = i & 31;
        int grow = rbase + r;
        float4 v = (grow < NN) ? ((const float4*)x)[(size_t)grow * 32 + c4]
                               : make_float4(0.f, 0.f, 0.f, 0.f);
        uint32_t h01, l01, h23, l23;
        splitpair(v.x, v.y, h01, l01);
        splitpair(v.z, v.w, h23, l23);
        *(uint2*)(sAh + r * APAD + 2 * c4) = make_uint2(h01, h23);
        *(uint2*)(sAl + r * APAD + 2 * c4) = make_uint2(l01, l23);
    }
    __syncthreads();

    const int warp = tid >> 5, lane = tid & 31, g = lane >> 2, tig = lane & 3;
    const uint32_t* a0h = sAh + (warp * 16 + g) * APAD;
    const uint32_t* a1h = sAh + (warp * 16 + g + 8) * APAD;
    const uint32_t* a0l = sAl + (warp * 16 + g) * APAD;
    const uint32_t* a1l = sAl + (warp * 16 + g + 8) * APAD;
    const int row0 = rbase + warp * 16 + g;
    const int row1 = row0 + 8;
    const uint2* gB = (const uint2*)g_B1u;   // hi [0,8192), lo [8192,16384)

    for (int nc = 0; nc < 8; nc++) {
        float acc[4][4] = {};
        #pragma unroll
        for (int kt = 0; kt < 8; kt++) {
            uint32_t ah0 = a0h[kt * 8 + tig], ah1 = a1h[kt * 8 + tig];
            uint32_t ah2 = a0h[kt * 8 + tig + 4], ah3 = a1h[kt * 8 + tig + 4];
            uint32_t al0 = a0l[kt * 8 + tig], al1 = a1l[kt * 8 + tig];
            uint32_t al2 = a0l[kt * 8 + tig + 4], al3 = a1l[kt * 8 + tig + 4];
            #pragma unroll
            for (int nt = 0; nt < 4; nt++) {
                int idx = (kt * 32 + nc * 4 + nt) * 32 + lane;
                uint2 bh = __ldg(gB + idx);
                uint2 bl = __ldg(gB + idx + 8192);
                mma_bf16(acc[nt], ah0, ah1, ah2, ah3, bh.x, bh.y);
                mma_bf16(acc[nt], al0, al1, al2, al3, bh.x, bh.y);
                mma_bf16(acc[nt], ah0, ah1, ah2, ah3, bl.x, bl.y);
            }
        }
        #pragma unroll
        for (int nt = 0; nt < 4; nt++) {
            int ncol = (nc * 4 + nt) * 8 + 2 * tig;
            if (ncol < 128) {
                float bb0 = __ldg(b1 + ncol), bb1 = __ldg(b1 + ncol + 1);
                if (row0 < NN)
                    *(float2*)(g_U + (size_t)row0 * H + ncol) =
                        make_float2(acc[nt][0] + bb0, acc[nt][1] + bb1);
                if (row1 < NN)
                    *(float2*)(g_U + (size_t)row1 * H + ncol) =
                        make_float2(acc[nt][2] + bb0, acc[nt][3] + bb1);
            } else {
                int vc = ncol - 128;
                if (row0 < NN)
                    *(float2*)(g_V + (size_t)row0 * H + vc) =
                        make_float2(acc[nt][0], acc[nt][1]);
                if (row1 < NN)
                    *(float2*)(g_V + (size_t)row1 * H + vc) =
                        make_float2(acc[nt][2], acc[nt][3]);
            }
        }
    }
}

// ---------------- agg kernel: warp per dst, no atomics ----------------
__global__ __launch_bounds__(256)
void agg_kernel() {
    const int lane = threadIdx.x & 31;
    const int gw = (blockIdx.x * blockDim.x + threadIdx.x) >> 5;
    const int nw = (gridDim.x * blockDim.x) >> 5;

    for (int d = gw; d < NN; d += nw) {
        float4 v = ((const float4*)(g_V + (size_t)d * H))[lane];
        float4 acc = make_float4(0.f, 0.f, 0.f, 0.f);
        float sw = 0.f;
        int i = g_off[d];
        const int end = g_off[d + 1];
        int s = 0; float w = 0.f;
        if (i < end) { s = __ldg(g_esrc + i); w = __ldg(g_eaw + i); }
        while (i < end) {
            float4 u = ((const float4*)(g_U + (size_t)s * H))[lane];
            int i2 = i + 1;
            int s2 = 0; float w2 = 0.f;
            if (i2 < end) { s2 = __ldg(g_esrc + i2); w2 = __ldg(g_eaw + i2); }
            acc.x += fmaxf(u.x + v.x, 0.f) * w;
            acc.y += fmaxf(u.y + v.y, 0.f) * w;
            acc.z += fmaxf(u.z + v.z, 0.f) * w;
            acc.w += fmaxf(u.w + v.w, 0.f) * w;
            sw += w;
            s = s2; w = w2; i = i2;
        }
        ((float4*)(g_S + (size_t)d * H))[lane] = acc;
        if (lane == 0) g_sumw[d] = sw;
    }
}

// ---------------- GEMM2 (mma): out = x + S@W2 + b2*sumw ----------------
__global__ __launch_bounds__(256, 3)
void gemm2_kernel(const float* __restrict__ x, const float* __restrict__ b2,
                  float* __restrict__ out) {
    extern __shared__ uint32_t sm[];
    uint32_t* sAh = sm;               // 128*68 = 8704
    uint32_t* sAl = sm + 8704;
    const int tid = threadIdx.x;
    const int rbase = blockIdx.x * 128;

    for (int i = tid; i < 128 * 32; i += 256) {
        int r = i >> 5, c4 = i & 31;
        int grow = rbase + r;
        float4 v = (grow < NN) ? ((const float4*)g_S)[(size_t)grow * 32 + c4]
                               : make_float4(0.f, 0.f, 0.f, 0.f);
        uint32_t h01, l01, h23, l23;
        splitpair(v.x, v.y, h01, l01);
        splitpair(v.z, v.w, h23, l23);
        *(uint2*)(sAh + r * APAD + 2 * c4) = make_uint2(h01, h23);
        *(uint2*)(sAl + r * APAD + 2 * c4) = make_uint2(l01, l23);
    }
    __syncthreads();

    const int warp = tid >> 5, lane = tid & 31, g = lane >> 2, tig = lane & 3;
    const uint32_t* a0h = sAh + (warp * 16 + g) * APAD;
    const uint32_t* a1h = sAh + (warp * 16 + g + 8) * APAD;
    const uint32_t* a0l = sAl + (warp * 16 + g) * APAD;
    const uint32_t* a1l = sAl + (warp * 16 + g + 8) * APAD;
    const int row0 = rbase + warp * 16 + g;
    const int row1 = row0 + 8;
    const float sw0 = (row0 < NN) ? g_sumw[row0] : 0.f;
    const float sw1 = (row1 < NN) ? g_sumw[row1] : 0.f;
    const uint2* gB = (const uint2*)g_B2u;   // hi [0,4096), lo [4096,8192)

    for (int nc = 0; nc < 4; nc++) {
        float acc[4][4] = {};
        #pragma unroll
        for (int kt = 0; kt < 8; kt++) {
            uint32_t ah0 = a0h[kt * 8 + tig], ah1 = a1h[kt * 8 + tig];
            uint32_t ah2 = a0h[kt * 8 + tig + 4], ah3 = a1h[kt * 8 + tig + 4];
            uint32_t al0 = a0l[kt * 8 + tig], al1 = a1l[kt * 8 + tig];
            uint32_t al2 = a0l[kt * 8 + tig + 4], al3 = a1l[kt * 8 + tig + 4];
            #pragma unroll
            for (int nt = 0; nt < 4; nt++) {
                int idx = (kt * 16 + nc * 4 + nt) * 32 + lane;
                uint2 bh = __ldg(gB + idx);
                uint2 bl = __ldg(gB + idx + 4096);
                mma_bf16(acc[nt], ah0, ah1, ah2, ah3, bh.x, bh.y);
                mma_bf16(acc[nt], al0, al1, al2, al3, bh.x, bh.y);
                mma_bf16(acc[nt], ah0, ah1, ah2, ah3, bl.x, bl.y);
            }
        }
        #pragma unroll
        for (int nt = 0; nt < 4; nt++) {
            int ncol = (nc * 4 + nt) * 8 + 2 * tig;
            float bb0 = __ldg(b2 + ncol), bb1 = __ldg(b2 + ncol + 1);
            if (row0 < NN) {
                float2 xr = *(const float2*)(x + (size_t)row0 * H + ncol);
                *(float2*)(out + (size_t)row0 * H + ncol) =
                    make_float2(xr.x + acc[nt][0] + bb0 * sw0,
                                xr.y + acc[nt][1] + bb1 * sw0);
            }
            if (row1 < NN) {
                float2 xr = *(const float2*)(x + (size_t)row1 * H + ncol);
                *(float2*)(out + (size_t)row1 * H + ncol) =
                    make_float2(xr.x + acc[nt][2] + bb0 * sw1,
                                xr.y + acc[nt][3] + bb1 * sw1);
            }
        }
    }
}

// ---------------- launch ----------------
extern "C" void kernel_launch(void* const* d_in, const int* in_sizes, int n_in,
                              void* d_out, int out_size) {
    (void)in_sizes; (void)n_in; (void)out_size;
    const float* x  = (const float*)d_in[0];
    const int*   ei = (const int*)d_in[1];
    const float* ea = (const float*)d_in[2];
    const float* W1 = (const float*)d_in[3];
    const float* b1 = (const float*)d_in[4];
    const float* W2 = (const float*)d_in[5];
    const float* b2 = (const float*)d_in[6];
    float* out = (float*)d_out;

    zero_cnt_kernel<<<(NN + 255) / 256, 256>>>();
    hist_kernel<<<(NE + 255) / 256, 256>>>(ei);
    scan_kernel<<<1, 1024>>>();
    scatter_kernel<<<(NE + 255) / 256, 256>>>(ei, ea);
    prep_B1<<<32, 256>>>(W1);
    prep_B2<<<16, 256>>>(W2);

    const size_t smemA = (size_t)(2 * 8704) * 4;        // 68 KB (A hi/lo)
    cudaFuncSetAttribute(gemm1_kernel, cudaFuncAttributeMaxDynamicSharedMemorySize, (int)smemA);
    gemm1_kernel<<<(NN + 127) / 128, 256, smemA>>>(x, b1);

    agg_kernel<<<2048, 256>>>();

    cudaFuncSetAttribute(gemm2_kernel, cudaFuncAttributeMaxDynamicSharedMemorySize, (int)smemA);
    gemm2_kernel<<<(NN + 127) / 128, 256, smemA>>>(x, b2, out);
}

// round 11
// speedup vs baseline: 1.0379x; 1.0379x over previous
#include <cuda_runtime.h>
#include <cuda_bf16.h>
#include <cstdint>

#define H        128
#define NE       500000
#define NN       50000
#define APAD     68                  // padded b32-pair row stride (64 + 4)

// ---------------- scratch (__device__ globals) ----------------
__device__ __align__(16) float g_U[NN * H];
__device__ __align__(16) float g_V[NN * H];
__device__ __align__(16) float g_S[NN * H];
__device__ __align__(16) float g_sumw[NN];
__device__ __align__(16) uint32_t g_B1u[32768];   // [hl][kt8][nt32][lane32][2]
__device__ __align__(16) uint32_t g_B2u[16384];   // [hl][kt8][nt16][lane32][2]

// ---------------- helpers ----------------
__device__ __forceinline__ void splitpair(float v0, float v1, uint32_t& h, uint32_t& l) {
    __nv_bfloat162 hh = __floats2bfloat162_rn(v0, v1);
    float r0 = v0 - __bfloat162float(hh.x);
    float r1 = v1 - __bfloat162float(hh.y);
    __nv_bfloat162 ll = __floats2bfloat162_rn(r0, r1);
    h = *(uint32_t*)&hh;
    l = *(uint32_t*)&ll;
}

__device__ __forceinline__ void mma_bf16(float* d,
                                         uint32_t a0, uint32_t a1, uint32_t a2, uint32_t a3,
                                         uint32_t b0, uint32_t b1) {
    asm("mma.sync.aligned.m16n8k16.row.col.f32.bf16.bf16.f32 "
        "{%0,%1,%2,%3}, {%4,%5,%6,%7}, {%8,%9}, {%0,%1,%2,%3};"
        : "+f"(d[0]), "+f"(d[1]), "+f"(d[2]), "+f"(d[3])
        : "r"(a0), "r"(a1), "r"(a2), "r"(a3), "r"(b0), "r"(b1));
}

// ---------------- zero S and sumw ----------------
__global__ void zero_kernel() {
    int i = blockIdx.x * blockDim.x + threadIdx.x;
    if (i < NN * H / 4) ((float4*)g_S)[i] = make_float4(0.f, 0.f, 0.f, 0.f);
    else if (i < NN * H / 4 + NN / 4)
        ((float4*)g_sumw)[i - NN * H / 4] = make_float4(0.f, 0.f, 0.f, 0.f);
}

// ---------------- prep: weight matrices -> bf16 hi/lo fragment images ----------------
__global__ void prep_B1(const float* __restrict__ W1) {   // [256,128]; Bcat[k][n]
    int i = blockIdx.x * blockDim.x + threadIdx.x;
    if (i >= 8192) return;
    int kt = i >> 10, nt = (i >> 5) & 31, lane = i & 31;
    int g = lane >> 2, tig = lane & 3;
    int n = nt * 8 + g;
    int k0 = kt * 16 + 2 * tig;
    float w[4];
    #pragma unroll
    for (int j = 0; j < 4; j++) {
        int k = k0 + (j >> 1) * 8 + (j & 1);
        w[j] = (n < 128) ? W1[(size_t)k * 128 + n]
                         : W1[(size_t)(128 + k) * 128 + (n - 128)];
    }
    uint32_t b0h, b0l, b1h, b1l;
    splitpair(w[0], w[1], b0h, b0l);
    splitpair(w[2], w[3], b1h, b1l);
    int base = ((kt * 32 + nt) * 32 + lane) * 2;
    g_B1u[base] = b0h; g_B1u[base + 1] = b1h;
    g_B1u[16384 + base] = b0l; g_B1u[16384 + base + 1] = b1l;
}

__global__ void prep_B2(const float* __restrict__ W2) {   // [128,128]
    int i = blockIdx.x * blockDim.x + threadIdx.x;
    if (i >= 4096) return;
    int kt = i >> 9, nt = (i >> 5) & 15, lane = i & 31;
    int g = lane >> 2, tig = lane & 3;
    int n = nt * 8 + g;
    int k0 = kt * 16 + 2 * tig;
    float w[4];
    #pragma unroll
    for (int j = 0; j < 4; j++) {
        int k = k0 + (j >> 1) * 8 + (j & 1);
        w[j] = W2[(size_t)k * 128 + n];
    }
    uint32_t b0h, b0l, b1h, b1l;
    splitpair(w[0], w[1], b0h, b0l);
    splitpair(w[2], w[3], b1h, b1l);
    int base = ((kt * 16 + nt) * 32 + lane) * 2;
    g_B2u[base] = b0h; g_B2u[base + 1] = b1h;
    g_B2u[8192 + base] = b0l; g_B2u[8192 + base + 1] = b1l;
}

// ---------------- GEMM1 (mma): U = x@W1a + b1 ; V = x@W1b ----------------
// 8 warps x 16 rows = 128 rows per CTA; N = 256; bh prefetched, bl on demand
__global__ __launch_bounds__(256, 2)
void gemm1_kernel(const float* __restrict__ x, const float* __restrict__ b1) {
    extern __shared__ uint32_t sm[];
    uint32_t* sAh = sm;              // 128*68 = 8704
    uint32_t* sAl = sm + 8704;
    const int tid = threadIdx.x;
    const int rbase = blockIdx.x * 128;

    for (int i = tid; i < 128 * 32; i += 256) {
        int r = i >> 5, c4 = i & 31;
        int grow = rbase + r;
        float4 v = (grow < NN) ? ((const float4*)x)[(size_t)grow * 32 + c4]
                               : make_float4(0.f, 0.f, 0.f, 0.f);
        uint32_t h01, l01, h23, l23;
        splitpair(v.x, v.y, h01, l01);
        splitpair(v.z, v.w, h23, l23);
        *(uint2*)(sAh + r * APAD + 2 * c4) = make_uint2(h01, h23);
        *(uint2*)(sAl + r * APAD + 2 * c4) = make_uint2(l01, l23);
    }
    __syncthreads();

    const int warp = tid >> 5, lane = tid & 31, g = lane >> 2, tig = lane & 3;
    const uint32_t* a0h = sAh + (warp * 16 + g) * APAD;
    const uint32_t* a1h = sAh + (warp * 16 + g + 8) * APAD;
    const uint32_t* a0l = sAl + (warp * 16 + g) * APAD;
    const uint32_t* a1l = sAl + (warp * 16 + g + 8) * APAD;
    const int row0 = rbase + warp * 16 + g;
    const int row1 = row0 + 8;
    const uint2* gB = (const uint2*)g_B1u;   // hi [0,8192), lo [8192,16384)

    for (int nc = 0; nc < 8; nc++) {
        float acc[4][4] = {};
        uint2 bh[4];
        #pragma unroll
        for (int nt = 0; nt < 4; nt++)
            bh[nt] = __ldg(gB + (nc * 4 + nt) * 32 + lane);       // kt = 0
        #pragma unroll
        for (int kt = 0; kt < 8; kt++) {
            uint2 nbh[4];
            if (kt < 7) {
                #pragma unroll
                for (int nt = 0; nt < 4; nt++)
                    nbh[nt] = __ldg(gB + ((kt + 1) * 32 + nc * 4 + nt) * 32 + lane);
            }
            uint32_t ah0 = a0h[kt * 8 + tig], ah1 = a1h[kt * 8 + tig];
            uint32_t ah2 = a0h[kt * 8 + tig + 4], ah3 = a1h[kt * 8 + tig + 4];
            uint32_t al0 = a0l[kt * 8 + tig], al1 = a1l[kt * 8 + tig];
            uint32_t al2 = a0l[kt * 8 + tig + 4], al3 = a1l[kt * 8 + tig + 4];
            #pragma unroll
            for (int nt = 0; nt < 4; nt++) {
                uint2 bl = __ldg(gB + (kt * 32 + nc * 4 + nt) * 32 + lane + 8192);
                mma_bf16(acc[nt], ah0, ah1, ah2, ah3, bh[nt].x, bh[nt].y);
                mma_bf16(acc[nt], al0, al1, al2, al3, bh[nt].x, bh[nt].y);
                mma_bf16(acc[nt], ah0, ah1, ah2, ah3, bl.x, bl.y);
            }
            if (kt < 7) {
                #pragma unroll
                for (int nt = 0; nt < 4; nt++) bh[nt] = nbh[nt];
            }
        }
        #pragma unroll
        for (int nt = 0; nt < 4; nt++) {
            int ncol = (nc * 4 + nt) * 8 + 2 * tig;
            if (ncol < 128) {
                float bb0 = __ldg(b1 + ncol), bb1 = __ldg(b1 + ncol + 1);
                if (row0 < NN)
                    *(float2*)(g_U + (size_t)row0 * H + ncol) =
                        make_float2(acc[nt][0] + bb0, acc[nt][1] + bb1);
                if (row1 < NN)
                    *(float2*)(g_U + (size_t)row1 * H + ncol) =
                        make_float2(acc[nt][2] + bb0, acc[nt][3] + bb1);
            } else {
                int vc = ncol - 128;
                if (row0 < NN)
                    *(float2*)(g_V + (size_t)row0 * H + vc) =
                        make_float2(acc[nt][0], acc[nt][1]);
                if (row1 < NN)
                    *(float2*)(g_V + (size_t)row1 * H + vc) =
                        make_float2(acc[nt][2], acc[nt][3]);
            }
        }
    }
}

// ---------------- edge kernel (proven R9 version) ----------------
__global__ __launch_bounds__(256)
void edge_kernel(const int* __restrict__ ei, const float* __restrict__ ea)
{
    const int lane = threadIdx.x & 31;
    const int gwarp = (blockIdx.x * blockDim.x + threadIdx.x) >> 5;
    const int nwarps = (gridDim.x * blockDim.x) >> 5;

    for (int e0 = gwarp * 4; e0 < NE; e0 += nwarps * 4) {
        int sn[4], dn[4]; float w[4]; float4 u[4], v[4];
        int cnt = (NE - e0 < 4) ? (NE - e0) : 4;
        #pragma unroll
        for (int j = 0; j < 4; j++) {
            int e = e0 + j;
            if (j < cnt) { sn[j] = __ldg(ei + e); dn[j] = __ldg(ei + NE + e); w[j] = __ldg(ea + e); }
            else { sn[j] = 0; dn[j] = 0; w[j] = 0.f; }
        }
        #pragma unroll
        for (int j = 0; j < 4; j++) {
            u[j] = ((const float4*)(g_U + (size_t)sn[j] * H))[lane];
            v[j] = ((const float4*)(g_V + (size_t)dn[j] * H))[lane];
        }
        #pragma unroll
        for (int j = 0; j < 4; j++) {
            if (j < cnt) {
                float a0 = fmaxf(u[j].x + v[j].x, 0.f) * w[j];
                float a1 = fmaxf(u[j].y + v[j].y, 0.f) * w[j];
                float a2 = fmaxf(u[j].z + v[j].z, 0.f) * w[j];
                float a3 = fmaxf(u[j].w + v[j].w, 0.f) * w[j];
                float* p = g_S + (size_t)dn[j] * H + 4 * lane;
                asm volatile("red.global.add.v4.f32 [%0], {%1,%2,%3,%4};"
                             :: "l"(p), "f"(a0), "f"(a1), "f"(a2), "f"(a3) : "memory");
                if (lane == 0)
                    asm volatile("red.global.add.f32 [%0], %1;"
                                 :: "l"(g_sumw + dn[j]), "f"(w[j]) : "memory");
            }
        }
    }
}

// ---------------- GEMM2 (mma): out = x + S@W2 + b2*sumw ----------------
__global__ __launch_bounds__(256, 2)
void gemm2_kernel(const float* __restrict__ x, const float* __restrict__ b2,
                  float* __restrict__ out) {
    extern __shared__ uint32_t sm[];
    uint32_t* sAh = sm;               // 128*68 = 8704
    uint32_t* sAl = sm + 8704;
    const int tid = threadIdx.x;
    const int rbase = blockIdx.x * 128;

    for (int i = tid; i < 128 * 32; i += 256) {
        int r = i >> 5, c4 = i & 31;
        int grow = rbase + r;
        float4 v = (grow < NN) ? ((const float4*)g_S)[(size_t)grow * 32 + c4]
                               : make_float4(0.f, 0.f, 0.f, 0.f);
        uint32_t h01, l01, h23, l23;
        splitpair(v.x, v.y, h01, l01);
        splitpair(v.z, v.w, h23, l23);
        *(uint2*)(sAh + r * APAD + 2 * c4) = make_uint2(h01, h23);
        *(uint2*)(sAl + r * APAD + 2 * c4) = make_uint2(l01, l23);
    }
    __syncthreads();

    const int warp = tid >> 5, lane = tid & 31, g = lane >> 2, tig = lane & 3;
    const uint32_t* a0h = sAh + (warp * 16 + g) * APAD;
    const uint32_t* a1h = sAh + (warp * 16 + g + 8) * APAD;
    const uint32_t* a0l = sAl + (warp * 16 + g) * APAD;
    const uint32_t* a1l = sAl + (warp * 16 + g + 8) * APAD;
    const int row0 = rbase + warp * 16 + g;
    const int row1 = row0 + 8;
    const float sw0 = (row0 < NN) ? g_sumw[row0] : 0.f;
    const float sw1 = (row1 < NN) ? g_sumw[row1] : 0.f;
    const uint2* gB = (const uint2*)g_B2u;   // hi [0,4096), lo [4096,8192)

    for (int nc = 0; nc < 4; nc++) {
        float acc[4][4] = {};
        uint2 bh[4];
        #pragma unroll
        for (int nt = 0; nt < 4; nt++)
            bh[nt] = __ldg(gB + (nc * 4 + nt) * 32 + lane);       // kt = 0
        #pragma unroll
        for (int kt = 0; kt < 8; kt++) {
            uint2 nbh[4];
            if (kt < 7) {
                #pragma unroll
                for (int nt = 0; nt < 4; nt++)
                    nbh[nt] = __ldg(gB + ((kt + 1) * 16 + nc * 4 + nt) * 32 + lane);
            }
            uint32_t ah0 = a0h[kt * 8 + tig], ah1 = a1h[kt * 8 + tig];
            uint32_t ah2 = a0h[kt * 8 + tig + 4], ah3 = a1h[kt * 8 + tig + 4];
            uint32_t al0 = a0l[kt * 8 + tig], al1 = a1l[kt * 8 + tig];
            uint32_t al2 = a0l[kt * 8 + tig + 4], al3 = a1l[kt * 8 + tig + 4];
            #pragma unroll
            for (int nt = 0; nt < 4; nt++) {
                uint2 bl = __ldg(gB + (kt * 16 + nc * 4 + nt) * 32 + lane + 4096);
                mma_bf16(acc[nt], ah0, ah1, ah2, ah3, bh[nt].x, bh[nt].y);
                mma_bf16(acc[nt], al0, al1, al2, al3, bh[nt].x, bh[nt].y);
                mma_bf16(acc[nt], ah0, ah1, ah2, ah3, bl.x, bl.y);
            }
            if (kt < 7) {
                #pragma unroll
                for (int nt = 0; nt < 4; nt++) bh[nt] = nbh[nt];
            }
        }
        #pragma unroll
        for (int nt = 0; nt < 4; nt++) {
            int ncol = (nc * 4 + nt) * 8 + 2 * tig;
            float bb0 = __ldg(b2 + ncol), bb1 = __ldg(b2 + ncol + 1);
            if (row0 < NN) {
                float2 xr = *(const float2*)(x + (size_t)row0 * H + ncol);
                *(float2*)(out + (size_t)row0 * H + ncol) =
                    make_float2(xr.x + acc[nt][0] + bb0 * sw0,
                                xr.y + acc[nt][1] + bb1 * sw0);
            }
            if (row1 < NN) {
                float2 xr = *(const float2*)(x + (size_t)row1 * H + ncol);
                *(float2*)(out + (size_t)row1 * H + ncol) =
                    make_float2(xr.x + acc[nt][2] + bb0 * sw1,
                                xr.y + acc[nt][3] + bb1 * sw1);
            }
        }
    }
}

// ---------------- launch ----------------
extern "C" void kernel_launch(void* const* d_in, const int* in_sizes, int n_in,
                              void* d_out, int out_size) {
    (void)in_sizes; (void)n_in; (void)out_size;
    const float* x  = (const float*)d_in[0];
    const int*   ei = (const int*)d_in[1];
    const float* ea = (const float*)d_in[2];
    const float* W1 = (const float*)d_in[3];
    const float* b1 = (const float*)d_in[4];
    const float* W2 = (const float*)d_in[5];
    const float* b2 = (const float*)d_in[6];
    float* out = (float*)d_out;

    const int nz = NN * H / 4 + NN / 4;
    zero_kernel<<<(nz + 255) / 256, 256>>>();
    prep_B1<<<32, 256>>>(W1);
    prep_B2<<<16, 256>>>(W2);

    const size_t smemA = (size_t)(2 * 8704) * 4;        // 68 KB (A hi/lo)
    cudaFuncSetAttribute(gemm1_kernel, cudaFuncAttributeMaxDynamicSharedMemorySize, (int)smemA);
    gemm1_kernel<<<(NN + 127) / 128, 256, smemA>>>(x, b1);   // launch #4 -> profiled

    edge_kernel<<<2048, 256>>>(ei, ea);

    cudaFuncSetAttribute(gemm2_kernel, cudaFuncAttributeMaxDynamicSharedMemorySize, (int)smemA);
    gemm2_kernel<<<(NN + 127) / 128, 256, smemA>>>(x, b2, out);
}